// round 11
// baseline (speedup 1.0000x reference)
#include <cuda_runtime.h>
#include <cuda_fp16.h>
#include <math.h>

#define NMAX 100000
#define EMAX 1600000
#define HID 64
#define NGRAPHS 64
#define JKDIM 192
#define SCAN_BLK 1024
#define MAX_SCAN_BLOCKS 128

// ---------------- scratch (device globals: no allocation allowed) ----------
__device__ int    g_deg[NMAX];
__device__ int    g_rowptr[NMAX + 1];
__device__ int    g_cursor[NMAX];
__device__ int    g_scanloc[NMAX];
__device__ int    g_blocksum[MAX_SCAN_BLOCKS];
__device__ int    g_blockoff[MAX_SCAN_BLOCKS];
__device__ int    g_csr_src[EMAX];
__device__ float  g_dinv[NMAX];
__device__ __half g_ysh[(size_t)NMAX * HID];  // dinv-scaled A@W, fp16
__device__ __half g_hh [(size_t)NMAX * HID];  // layer activations, fp16
__device__ float  g_pooled[NGRAPHS * JKDIM];
__device__ float  g_cnt[NGRAPHS];

__device__ __forceinline__ unsigned int h2bits(__half2 h) {
    return *(unsigned int*)&h;
}
__device__ __forceinline__ unsigned int smem_u32(const void* p) {
    unsigned int a;
    asm("{ .reg .u64 t; cvta.to.shared.u64 t, %1; cvt.u32.u64 %0, t; }"
        : "=r"(a) : "l"(p));
    return a;
}

// ---------------- init ------------------------------------------------------
__global__ void zero_kernel(int N) {
    int i = blockIdx.x * blockDim.x + threadIdx.x;
    if (i < N) g_deg[i] = 0;
    if (i < NGRAPHS * JKDIM) g_pooled[i] = 0.f;
    if (i < NGRAPHS) g_cnt[i] = 0.f;
}

__global__ void degree_kernel(const int* __restrict__ ei, int E) {
    int e = blockIdx.x * blockDim.x + threadIdx.x;
    if (e < E) atomicAdd(&g_deg[ei[E + e]], 1);
}

// ---------------- scan (also computes dinv) ----------------------------------
__global__ __launch_bounds__(SCAN_BLK) void block_scan_kernel(int N) {
    __shared__ int bs[SCAN_BLK];
    int t = threadIdx.x;
    int i = blockIdx.x * SCAN_BLK + t;
    int v = (i < N) ? g_deg[i] : 0;
    if (i < N) g_dinv[i] = rsqrtf((float)(v + 1));  // +1 self loop
    bs[t] = v;
    __syncthreads();
#pragma unroll
    for (int off = 1; off < SCAN_BLK; off <<= 1) {
        int u = (t >= off) ? bs[t - off] : 0;
        __syncthreads();
        bs[t] += u;
        __syncthreads();
    }
    if (i < N) g_scanloc[i] = bs[t] - v;
    if (t == SCAN_BLK - 1) g_blocksum[blockIdx.x] = bs[t];
}

__global__ void scan_blocksums_kernel(int nb) {
    __shared__ int bs[MAX_SCAN_BLOCKS];
    int t = threadIdx.x;
    int v = (t < nb) ? g_blocksum[t] : 0;
    bs[t] = v;
    __syncthreads();
#pragma unroll
    for (int off = 1; off < MAX_SCAN_BLOCKS; off <<= 1) {
        int u = (t >= off) ? bs[t - off] : 0;
        __syncthreads();
        bs[t] += u;
        __syncthreads();
    }
    if (t < nb) g_blockoff[t] = bs[t] - v;
}

__global__ void apply_offsets_kernel(int N, int E) {
    int i = blockIdx.x * blockDim.x + threadIdx.x;
    if (i < N) {
        int r = g_scanloc[i] + g_blockoff[i / SCAN_BLK];
        g_rowptr[i] = r;
        g_cursor[i] = r;
    }
    if (i == 0) g_rowptr[N] = E;
}

__global__ void fill_kernel(const int* __restrict__ ei, int E) {
    int e = blockIdx.x * blockDim.x + threadIdx.x;
    if (e < E) {
        int d = ei[E + e];
        int pos = atomicAdd(&g_cursor[d], 1);
        g_csr_src[pos] = ei[e];
    }
}

// -------- HMMA GEMM: ysh = fp16((A @ W) * dinv[row]) ------------------------
template <int KTOT, bool FP16IN>
__global__ __launch_bounds__(256) void gemm_hmma(const float* __restrict__ Af,
                                                 const float* __restrict__ W,
                                                 int N) {
    __shared__ __half As[128][40];
    __shared__ __half Bs[32][72];

    int tid = threadIdx.x;
    int warp = tid >> 5;
    int lane = tid & 31;
    int rowBase = blockIdx.x * 128;
    int wrow = warp * 16;

    float acc[8][4];
#pragma unroll
    for (int i = 0; i < 8; i++)
#pragma unroll
        for (int j = 0; j < 4; j++) acc[i][j] = 0.f;

    for (int kc = 0; kc < KTOT; kc += 32) {
        {
            int ar = tid >> 1;
            int ak = (tid & 1) * 16;
            int grow = rowBase + ar;
            uint4 u0 = make_uint4(0, 0, 0, 0);
            uint4 u1 = make_uint4(0, 0, 0, 0);
            if (FP16IN) {
                if (grow < N) {
                    const uint4* p = (const uint4*)(g_hh + (size_t)grow * KTOT + kc + ak);
                    u0 = p[0];
                    u1 = p[1];
                }
            } else {
                if (grow < N) {
                    const float4* p = (const float4*)(Af + (size_t)grow * KTOT + kc + ak);
                    float4 f0 = p[0], f1 = p[1], f2 = p[2], f3 = p[3];
                    u0.x = h2bits(__floats2half2_rn(f0.x, f0.y));
                    u0.y = h2bits(__floats2half2_rn(f0.z, f0.w));
                    u0.z = h2bits(__floats2half2_rn(f1.x, f1.y));
                    u0.w = h2bits(__floats2half2_rn(f1.z, f1.w));
                    u1.x = h2bits(__floats2half2_rn(f2.x, f2.y));
                    u1.y = h2bits(__floats2half2_rn(f2.z, f2.w));
                    u1.z = h2bits(__floats2half2_rn(f3.x, f3.y));
                    u1.w = h2bits(__floats2half2_rn(f3.z, f3.w));
                }
            }
            *(uint4*)&As[ar][ak] = u0;
            *(uint4*)&As[ar][ak + 8] = u1;
        }
        {
            int br = tid >> 3;
            int bc = (tid & 7) * 8;
            const float4* p = (const float4*)(W + (size_t)(kc + br) * 64 + bc);
            float4 w0 = p[0], w1 = p[1];
            uint4 u;
            u.x = h2bits(__floats2half2_rn(w0.x, w0.y));
            u.y = h2bits(__floats2half2_rn(w0.z, w0.w));
            u.z = h2bits(__floats2half2_rn(w1.x, w1.y));
            u.w = h2bits(__floats2half2_rn(w1.z, w1.w));
            *(uint4*)&Bs[br][bc] = u;
        }
        __syncthreads();

#pragma unroll
        for (int c = 0; c < 2; c++) {
            unsigned int a0, a1, a2, a3;
            unsigned int aaddr =
                smem_u32(&As[wrow + (lane & 15)][c * 16 + (lane >> 4) * 8]);
            asm volatile(
                "ldmatrix.sync.aligned.m8n8.x4.shared.b16 {%0,%1,%2,%3}, [%4];"
                : "=r"(a0), "=r"(a1), "=r"(a2), "=r"(a3) : "r"(aaddr));

#pragma unroll
            for (int nb = 0; nb < 8; nb += 2) {
                unsigned int b0, b1, b2, b3;
                unsigned int baddr =
                    smem_u32(&Bs[c * 16 + (lane & 15)][nb * 8 + (lane >> 4) * 8]);
                asm volatile(
                    "ldmatrix.sync.aligned.m8n8.x4.trans.shared.b16 {%0,%1,%2,%3}, [%4];"
                    : "=r"(b0), "=r"(b1), "=r"(b2), "=r"(b3) : "r"(baddr));
                asm volatile(
                    "mma.sync.aligned.m16n8k16.row.col.f32.f16.f16.f32 "
                    "{%0,%1,%2,%3}, {%4,%5,%6,%7}, {%8,%9}, {%0,%1,%2,%3};"
                    : "+f"(acc[nb][0]), "+f"(acc[nb][1]),
                      "+f"(acc[nb][2]), "+f"(acc[nb][3])
                    : "r"(a0), "r"(a1), "r"(a2), "r"(a3), "r"(b0), "r"(b1));
                asm volatile(
                    "mma.sync.aligned.m16n8k16.row.col.f32.f16.f16.f32 "
                    "{%0,%1,%2,%3}, {%4,%5,%6,%7}, {%8,%9}, {%0,%1,%2,%3};"
                    : "+f"(acc[nb + 1][0]), "+f"(acc[nb + 1][1]),
                      "+f"(acc[nb + 1][2]), "+f"(acc[nb + 1][3])
                    : "r"(a0), "r"(a1), "r"(a2), "r"(a3), "r"(b2), "r"(b3));
            }
        }
        __syncthreads();
    }

    int gID = lane >> 2;
    int tID = lane & 3;
    int r0 = rowBase + wrow + gID;
    int r1 = r0 + 8;
    float dv0 = (r0 < N) ? g_dinv[r0] : 0.f;
    float dv1 = (r1 < N) ? g_dinv[r1] : 0.f;
#pragma unroll
    for (int nb = 0; nb < 8; nb++) {
        int col = nb * 8 + tID * 2;
        if (r0 < N) {
            __half2 p = __floats2half2_rn(acc[nb][0] * dv0, acc[nb][1] * dv0);
            *(__half2*)(g_ysh + (size_t)r0 * HID + col) = p;
        }
        if (r1 < N) {
            __half2 p = __floats2half2_rn(acc[nb][2] * dv1, acc[nb][3] * dv1);
            *(__half2*)(g_ysh + (size_t)r1 * HID + col) = p;
        }
    }
}

// ---- aggregation: 32 thr/node (max concurrency), fp16 gather ---------------
// h[n] = relu(dinv[n]*(ysh[n] + sum ysh[src]) + b)
__device__ __forceinline__ void add_h2(float2& acc, unsigned int v) {
    float2 f = __half22float2(*(__half2*)&v);
    acc.x += f.x;
    acc.y += f.y;
}

__global__ __launch_bounds__(256) void aggregate_kernel(
    const float* __restrict__ bias, const int* __restrict__ batch,
    int off, int doPool, int doCount, int writeH, int N) {
    int gid = blockIdx.x * blockDim.x + threadIdx.x;
    int node = gid >> 5;
    int sl = gid & 31;            // one half2 (4 bytes) per thread
    bool valid = node < N;

    const unsigned int* __restrict__ ysv = (const unsigned int*)g_ysh; // 32/row

    float2 h2 = make_float2(0.f, 0.f);

    if (valid) {
        int beg = __ldg(&g_rowptr[node]);
        int end = __ldg(&g_rowptr[node + 1]);
        float dvn = __ldg(&g_dinv[node]);

        float2 s0 = make_float2(0.f, 0.f);
        float2 s1 = make_float2(0.f, 0.f);
        float2 s2 = make_float2(0.f, 0.f);
        float2 s3 = make_float2(0.f, 0.f);
        add_h2(s0, __ldg(&ysv[(size_t)node * 32 + sl]));  // self loop

        int e = beg;
        for (; e + 4 <= end; e += 4) {
            int a0 = __ldg(&g_csr_src[e]);
            int a1 = __ldg(&g_csr_src[e + 1]);
            int a2 = __ldg(&g_csr_src[e + 2]);
            int a3 = __ldg(&g_csr_src[e + 3]);
            unsigned int v0 = __ldg(&ysv[(size_t)a0 * 32 + sl]);
            unsigned int v1 = __ldg(&ysv[(size_t)a1 * 32 + sl]);
            unsigned int v2 = __ldg(&ysv[(size_t)a2 * 32 + sl]);
            unsigned int v3 = __ldg(&ysv[(size_t)a3 * 32 + sl]);
            add_h2(s0, v0); add_h2(s1, v1);
            add_h2(s2, v2); add_h2(s3, v3);
        }
        for (; e < end; e++) {
            int a0 = __ldg(&g_csr_src[e]);
            add_h2(s0, __ldg(&ysv[(size_t)a0 * 32 + sl]));
        }

        float2 b2 = *(const float2*)(bias + sl * 2);
        float sx = (s0.x + s1.x) + (s2.x + s3.x);
        float sy = (s0.y + s1.y) + (s2.y + s3.y);
        h2.x = fmaxf(sx * dvn + b2.x, 0.f);
        h2.y = fmaxf(sy * dvn + b2.y, 0.f);

        if (writeH) {
            unsigned int st = h2bits(__floats2half2_rn(h2.x, h2.y));
            *(unsigned int*)(g_hh + (size_t)node * HID + sl * 2) = st;
        }
    }

    if (doPool) {
        __shared__ float sh[8][64];
        __shared__ int sg[8];
        int nl = threadIdx.x >> 5;
        int sli = threadIdx.x & 31;
        *(float2*)&sh[nl][sli * 2] = h2;
        if (sli == 0) sg[nl] = valid ? __ldg(&batch[node]) : -1;
        __syncthreads();

        if (threadIdx.x < 64) {
            int gmin = 0x7fffffff, gmax = -1;
#pragma unroll
            for (int i = 0; i < 8; i++) {
                int g = sg[i];
                if (g >= 0) { gmin = min(gmin, g); gmax = max(gmax, g); }
            }
            for (int g = gmin; g <= gmax; g++) {
                float s = 0.f;
                int cnt = 0;
#pragma unroll
                for (int i = 0; i < 8; i++)
                    if (sg[i] == g) { s += sh[i][threadIdx.x]; cnt++; }
                atomicAdd(&g_pooled[g * JKDIM + off + threadIdx.x], s);
                if (doCount && threadIdx.x == 0) atomicAdd(&g_cnt[g], (float)cnt);
            }
        }
    }
}

// ---------------- head: mean-pool normalize + linear + log_softmax ----------
__global__ void head_kernel(const float* __restrict__ Wl,
                            const float* __restrict__ bl,
                            float* __restrict__ out) {
    int g = threadIdx.x;
    if (g >= NGRAPHS) return;
    float ic = 1.f / fmaxf(g_cnt[g], 1.f);
    float logit[10];
#pragma unroll
    for (int j = 0; j < 10; j++) logit[j] = bl[j];
    for (int k = 0; k < JKDIM; k++) {
        float v = g_pooled[g * JKDIM + k] * ic;
#pragma unroll
        for (int j = 0; j < 10; j++) logit[j] += v * Wl[k * 10 + j];
    }
    float m = logit[0];
#pragma unroll
    for (int j = 1; j < 10; j++) m = fmaxf(m, logit[j]);
    float s = 0.f;
#pragma unroll
    for (int j = 0; j < 10; j++) s += expf(logit[j] - m);
    float lse = logf(s);
#pragma unroll
    for (int j = 0; j < 10; j++) out[g * 10 + j] = logit[j] - m - lse;
}

// ---------------- launch -----------------------------------------------------
extern "C" void kernel_launch(void* const* d_in, const int* in_sizes, int n_in,
                              void* d_out, int out_size) {
    const float* x  = (const float*)d_in[0];
    const float* W1 = (const float*)d_in[1];
    const float* b1 = (const float*)d_in[2];
    const float* W2 = (const float*)d_in[3];
    const float* b2 = (const float*)d_in[4];
    const float* W3 = (const float*)d_in[5];
    const float* b3 = (const float*)d_in[6];
    const float* W4 = (const float*)d_in[7];
    const float* b4 = (const float*)d_in[8];
    const float* Wl = (const float*)d_in[9];
    const float* bl = (const float*)d_in[10];
    const int* ei    = (const int*)d_in[11];
    const int* batch = (const int*)d_in[12];
    float* out = (float*)d_out;

    int N = in_sizes[12];
    int E = in_sizes[11] / 2;

    int threads = 256;
    int gridN = (N + threads - 1) / threads;
    int gridE = (E + threads - 1) / threads;
    int gemmGrid = (N + 127) / 128;
    long long aggThreads = (long long)N * 32;
    int aggGrid = (int)((aggThreads + threads - 1) / threads);
    int nScanBlocks = (N + SCAN_BLK - 1) / SCAN_BLK;

    // one-time host-side stream/event resources (no device memory involved)
    static cudaStream_t s2 = nullptr;
    static cudaEvent_t evFork = nullptr, evJoin = nullptr;
    if (!s2) {
        cudaStreamCreateWithFlags(&s2, cudaStreamNonBlocking);
        cudaEventCreateWithFlags(&evFork, cudaEventDisableTiming);
        cudaEventCreateWithFlags(&evJoin, cudaEventDisableTiming);
    }

    zero_kernel<<<gridN, threads>>>(N);
    degree_kernel<<<gridE, threads>>>(ei, E);
    block_scan_kernel<<<nScanBlocks, SCAN_BLK>>>(N);   // dinv ready after this

    // fork: gemm1 (needs only x, W1, dinv) overlaps rest of CSR build
    cudaEventRecord(evFork, 0);
    cudaStreamWaitEvent(s2, evFork, 0);
    gemm_hmma<128, false><<<gemmGrid, 256, 0, s2>>>(x, W1, N);
    cudaEventRecord(evJoin, s2);

    scan_blocksums_kernel<<<1, MAX_SCAN_BLOCKS>>>(nScanBlocks);
    apply_offsets_kernel<<<gridN, threads>>>(N, E);
    fill_kernel<<<gridE, threads>>>(ei, E);

    cudaStreamWaitEvent(0, evJoin, 0);

    // layer 1; pool x1 -> [0:64), counts
    aggregate_kernel<<<aggGrid, threads>>>(b1, batch, 0, 1, 1, 1, N);

    // layer 2; pool x2 -> [64:128)
    gemm_hmma<64, true><<<gemmGrid, 256>>>(nullptr, W2, N);
    aggregate_kernel<<<aggGrid, threads>>>(b2, batch, 64, 1, 0, 1, N);

    // layer 3 (no pool)
    gemm_hmma<64, true><<<gemmGrid, 256>>>(nullptr, W3, N);
    aggregate_kernel<<<aggGrid, threads>>>(b3, batch, 0, 0, 0, 1, N);

    // layer 4 (overwrites x3); pool -> [128:192); h never read again
    gemm_hmma<64, true><<<gemmGrid, 256>>>(nullptr, W4, N);
    aggregate_kernel<<<aggGrid, threads>>>(b4, batch, 128, 1, 0, 0, N);

    head_kernel<<<1, 64>>>(Wl, bl, out);
}